// round 13
// baseline (speedup 1.0000x reference)
#include <cuda_runtime.h>
#include <cuda_bf16.h>

// ---------------------------------------------------------------------------
// MLP_TI_Gram: y = MLP(mean-of-shifted-diagonal of per-batch Gram matrix)
// diag-mean == circular autocorrelation == FFT(sum_d |FFT(x_d)|^2)/N^2
// (Wiener-Khinchin; P real-even so inverse == forward FFT, real part).
// B=128, N=1024, H=128.
// fftcorr: radix-4 Stockham, fused ends, and the two forward signals run in
// DECOUPLED 8-warp barrier domains (named barriers + private twiddle tables).
// Pipeline: fftcorr -> gemm1 (PDL) -> mlp23 (PDL).
// ---------------------------------------------------------------------------

#define BATCH 128
#define NSEQ  1024
#define HID   128

typedef unsigned long long u64;

__device__ float g_c[BATCH * NSEQ];    // correlation (scratch)
__device__ float g_h1[BATCH * HID];    // layer-1 activations (scratch)

// ---- f32x2 packed helpers (Blackwell, PTX-only) ---------------------------
__device__ __forceinline__ u64 pk2(float lo, float hi) {
    u64 r;
    asm("mov.b64 %0, {%1,%2};" : "=l"(r) : "f"(lo), "f"(hi));
    return r;
}
__device__ __forceinline__ void upk2(u64 v, float& lo, float& hi) {
    asm("mov.b64 {%0,%1}, %2;" : "=f"(lo), "=f"(hi) : "l"(v));
}
__device__ __forceinline__ u64 fma2(u64 a, u64 b, u64 c) {
    u64 d;
    asm("fma.rn.f32x2 %0, %1, %2, %3;" : "=l"(d) : "l"(a), "l"(b), "l"(c));
    return d;
}
__device__ __forceinline__ u64 add2(u64 a, u64 b) {
    u64 d;
    asm("add.rn.f32x2 %0, %1, %2;" : "=l"(d) : "l"(a), "l"(b));
    return d;
}

__device__ __forceinline__ float celu1(float v) {
    return v > 0.0f ? v : expm1f(v);
}
__device__ __forceinline__ float2 cmul(float2 a, float2 b) {
    return make_float2(a.x * b.x - a.y * b.y, a.x * b.y + a.y * b.x);
}

// named barrier: id, thread count (must be whole warps)
__device__ __forceinline__ void barx(int id, int cnt) {
    asm volatile("bar.sync %0, %1;" :: "r"(id), "r"(cnt) : "memory");
}

// ---- PDL primitives --------------------------------------------------------
__device__ __forceinline__ void pdl_wait() {
    asm volatile("griddepcontrol.wait;" ::: "memory");
}
__device__ __forceinline__ void pdl_trigger() {
    asm volatile("griddepcontrol.launch_dependents;" ::: "memory");
}

// ---------------------------------------------------------------------------
// Kernel 1: correlation via FFT, radix-4 Stockham, fused ends, decoupled
// signal groups. 128 blocks (one per batch), 512 threads.
// Group f (warps 8f..8f+7) owns signal f through the whole forward pass:
// private twiddle table twg[f], private buffers bufA/B[f], named barrier 1+f.
// Single full join before the PS-fused inverse; inverse runs on group 0 with
// 256-scope barriers.
// ---------------------------------------------------------------------------
__global__ __launch_bounds__(512, 1)
void fftcorr_kernel(const float* __restrict__ x) {
    __shared__ float2 bufA[2][1024];   // 16KB
    __shared__ float2 bufB[2][1024];   // 16KB
    __shared__ float2 twg[2][256];     // per-group W_1024^m, m in [0,256)

    const int b = blockIdx.x;
    const int t = threadIdx.x;
    const int f = t >> 8;              // signal group (0: ch0+i*ch1, 1: ch2)
    const int i = t & 255;             // butterfly index within group

    // private twiddle table: twg[f][m] = exp(-2*pi*i*m/1024), m < 256
    {
        float s_, c_;
        sincospif(-(float)i * (1.0f / 512.0f), &s_, &c_);
        twg[f][i] = make_float2(c_, s_);
    }
    const float2* __restrict__ tw = twg[f];

    const float* __restrict__ xb = x + (size_t)b * NSEQ * 3;

    // ---- forward stage 0 (s=0, w=1): load x directly from gmem ----
    {
        float2 a0, a1, a2, a3;
        if (f == 0) {
            a0 = make_float2(xb[3 * i],           xb[3 * i + 1]);
            a1 = make_float2(xb[3 * (i + 256)],   xb[3 * (i + 256) + 1]);
            a2 = make_float2(xb[3 * (i + 512)],   xb[3 * (i + 512) + 1]);
            a3 = make_float2(xb[3 * (i + 768)],   xb[3 * (i + 768) + 1]);
        } else {
            a0 = make_float2(xb[3 * i + 2],         0.0f);
            a1 = make_float2(xb[3 * (i + 256) + 2], 0.0f);
            a2 = make_float2(xb[3 * (i + 512) + 2], 0.0f);
            a3 = make_float2(xb[3 * (i + 768) + 2], 0.0f);
        }
        float2 t02p = make_float2(a0.x + a2.x, a0.y + a2.y);
        float2 t02m = make_float2(a0.x - a2.x, a0.y - a2.y);
        float2 t13p = make_float2(a1.x + a3.x, a1.y + a3.y);
        float2 t13m = make_float2(a1.x - a3.x, a1.y - a3.y);
        const int d = i << 2;
        bufA[f][d]     = make_float2(t02p.x + t13p.x, t02p.y + t13p.y);
        bufA[f][d + 1] = make_float2(t02m.x + t13m.y, t02m.y - t13m.x);
        bufA[f][d + 2] = make_float2(t02p.x - t13p.x, t02p.y - t13p.y);
        bufA[f][d + 3] = make_float2(t02m.x - t13m.y, t02m.y + t13m.x);
    }
    barx(1 + f, 256);   // group-local join (also covers twg[f] init)

    // ---- forward stages 1..3 (group-local barriers) ----
    {
        float2 (*src)[1024] = bufA;
        float2 (*dst)[1024] = bufB;
#pragma unroll
        for (int s = 1; s < 4; s++) {
            const int L = 1 << (2 * s);
            const int q = i & (L - 1);
            const int d = ((i >> (2 * s)) << (2 * s + 2)) | q;
            const float2 w1t = tw[q << (8 - 2 * s)];
            const float2 w2t = make_float2(w1t.x * w1t.x - w1t.y * w1t.y,
                                           2.0f * w1t.x * w1t.y);
            const float2 w3t = cmul(w2t, w1t);

            float2 a0 = src[f][i];
            float2 a1 = src[f][i + 256];
            float2 a2 = src[f][i + 512];
            float2 a3 = src[f][i + 768];
            float2 b1 = cmul(a1, w1t);
            float2 b2 = cmul(a2, w2t);
            float2 b3 = cmul(a3, w3t);

            float2 t02p = make_float2(a0.x + b2.x, a0.y + b2.y);
            float2 t02m = make_float2(a0.x - b2.x, a0.y - b2.y);
            float2 t13p = make_float2(b1.x + b3.x, b1.y + b3.y);
            float2 t13m = make_float2(b1.x - b3.x, b1.y - b3.y);

            dst[f][d]         = make_float2(t02p.x + t13p.x, t02p.y + t13p.y);
            dst[f][d + L]     = make_float2(t02m.x + t13m.y, t02m.y - t13m.x);
            dst[f][d + 2 * L] = make_float2(t02p.x - t13p.x, t02p.y - t13p.y);
            dst[f][d + 3 * L] = make_float2(t02m.x - t13m.y, t02m.y + t13m.x);

            float2 (*tmp)[1024] = src; src = dst; dst = tmp;
            barx(1 + f, 256);
        }
    }
    // 3 passes: A->B->A->B  => stage-3 output in bufB

    // ---- forward stage 4 (last), then FULL join ----
    {
        const int q = i;                 // L = 256
        const int d = i;                 // ((i>>8)<<10)|q = q
        const float2 w1t = tw[q];
        const float2 w2t = make_float2(w1t.x * w1t.x - w1t.y * w1t.y,
                                       2.0f * w1t.x * w1t.y);
        const float2 w3t = cmul(w2t, w1t);

        float2 a0 = bufB[f][i];
        float2 a1 = bufB[f][i + 256];
        float2 a2 = bufB[f][i + 512];
        float2 a3 = bufB[f][i + 768];
        float2 b1 = cmul(a1, w1t);
        float2 b2 = cmul(a2, w2t);
        float2 b3 = cmul(a3, w3t);

        float2 t02p = make_float2(a0.x + b2.x, a0.y + b2.y);
        float2 t02m = make_float2(a0.x - b2.x, a0.y - b2.y);
        float2 t13p = make_float2(b1.x + b3.x, b1.y + b3.y);
        float2 t13m = make_float2(b1.x - b3.x, b1.y - b3.y);

        bufA[f][d]       = make_float2(t02p.x + t13p.x, t02p.y + t13p.y);
        bufA[f][d + 256] = make_float2(t02m.x + t13m.y, t02m.y - t13m.x);
        bufA[f][d + 512] = make_float2(t02p.x - t13p.x, t02p.y - t13p.y);
        bufA[f][d + 768] = make_float2(t02m.x - t13m.y, t02m.y + t13m.x);
    }
    __syncthreads();   // full join: spectra of both signals in bufA

    // ---- inverse stage 0 (s=0, w=1) fused with power spectrum (group 0) ----
    if (t < 256) {
        float P[4];
#pragma unroll
        for (int r = 0; r < 4; r++) {
            int k = t + 256 * r;
            int m = (1024 - k) & 1023;
            float2 z  = bufA[0][k];
            float2 zm = bufA[0][m];
            float2 z2 = bufA[1][k];
            P[r] = 0.5f * (z.x * z.x + z.y * z.y + zm.x * zm.x + zm.y * zm.y)
                 + (z2.x * z2.x + z2.y * z2.y);
        }
        float p02p = P[0] + P[2];
        float p02m = P[0] - P[2];
        float p13p = P[1] + P[3];
        float p13m = P[1] - P[3];
        const int d = t << 2;
        bufB[0][d]     = make_float2(p02p + p13p, 0.0f);
        bufB[0][d + 1] = make_float2(p02m, -p13m);
        bufB[0][d + 2] = make_float2(p02p - p13p, 0.0f);
        bufB[0][d + 3] = make_float2(p02m,  p13m);

        barx(1, 256);

        // ---- inverse stages 1..3 (group-0 barriers) ----
        float2 (*src)[1024] = bufB;
        float2 (*dst)[1024] = bufA;
#pragma unroll
        for (int s = 1; s < 4; s++) {
            const int L = 1 << (2 * s);
            const int q = t & (L - 1);
            const int d2 = ((t >> (2 * s)) << (2 * s + 2)) | q;
            const float2 w1t = tw[q << (8 - 2 * s)];
            const float2 w2t = make_float2(w1t.x * w1t.x - w1t.y * w1t.y,
                                           2.0f * w1t.x * w1t.y);
            const float2 w3t = cmul(w2t, w1t);

            float2 a0 = src[0][t];
            float2 a1 = src[0][t + 256];
            float2 a2 = src[0][t + 512];
            float2 a3 = src[0][t + 768];
            float2 b1 = cmul(a1, w1t);
            float2 b2 = cmul(a2, w2t);
            float2 b3 = cmul(a3, w3t);

            float2 t02p = make_float2(a0.x + b2.x, a0.y + b2.y);
            float2 t02m = make_float2(a0.x - b2.x, a0.y - b2.y);
            float2 t13p = make_float2(b1.x + b3.x, b1.y + b3.y);
            float2 t13m = make_float2(b1.x - b3.x, b1.y - b3.y);

            dst[0][d2]         = make_float2(t02p.x + t13p.x, t02p.y + t13p.y);
            dst[0][d2 + L]     = make_float2(t02m.x + t13m.y, t02m.y - t13m.x);
            dst[0][d2 + 2 * L] = make_float2(t02p.x - t13p.x, t02p.y - t13p.y);
            dst[0][d2 + 3 * L] = make_float2(t02m.x - t13m.y, t02m.y + t13m.x);

            float2 (*tmp)[1024] = src; src = dst; dst = tmp;
            barx(1, 256);
        }
        // 3 passes: B->A->B->A  => stage-3 output in bufA

        // ---- inverse stage 4 (s=4): fused scaled store to g_c ----
        {
            const float2 w1t = tw[t];     // q = t, L = 256
            const float2 w2t = make_float2(w1t.x * w1t.x - w1t.y * w1t.y,
                                           2.0f * w1t.x * w1t.y);
            const float2 w3t = cmul(w2t, w1t);

            float2 a0 = bufA[0][t];
            float2 a1 = bufA[0][t + 256];
            float2 a2 = bufA[0][t + 512];
            float2 a3 = bufA[0][t + 768];
            float2 b1 = cmul(a1, w1t);
            float2 b2 = cmul(a2, w2t);
            float2 b3 = cmul(a3, w3t);

            float t02px = a0.x + b2.x;
            float t02mx = a0.x - b2.x;
            float t13px = b1.x + b3.x;
            float t13my = b1.y - b3.y;

            const float inv = 1.0f / (1024.0f * 1024.0f);
            float* __restrict__ cb = g_c + (size_t)b * NSEQ;
            cb[t]       = (t02px + t13px) * inv;
            cb[t + 256] = (t02mx + t13my) * inv;
            cb[t + 512] = (t02px - t13px) * inv;
            cb[t + 768] = (t02mx - t13my) * inv;
        }
    }

    // all g_c stores (by warps 0-7) must complete before ANY thread triggers
    __threadfence();
    __syncthreads();
    pdl_trigger();
}

// ---------------------------------------------------------------------------
// Kernel 2: tiled layer-1 GEMM (PDL consumer). W1 staged pre-wait.
// Grid 128 = 16 batch-tiles (8 batches) x 8 h-tiles (16 h). 512 threads.
// ---------------------------------------------------------------------------
#define CSH_PITCH 1025
#define RED_PITCH 66
#define GEMM1_SMEM ((4 * CSH_PITCH + 1024 * 16 + 32 * RED_PITCH) * 8)

__global__ __launch_bounds__(512, 1)
void gemm1_kernel(const float* __restrict__ W1, const float* __restrict__ b1) {
    extern __shared__ char dsm[];
    u64 (*csh)[CSH_PITCH] = (u64(*)[CSH_PITCH])dsm;
    u64 (*w1d)[16]        = (u64(*)[16])(dsm + 4 * CSH_PITCH * 8);
    u64 (*red)[RED_PITCH] = (u64(*)[RED_PITCH])(dsm + (4 * CSH_PITCH + 1024 * 16) * 8);

    const int t  = threadIdx.x;
    const int bt = blockIdx.x >> 3;
    const int ht = blockIdx.x & 7;
    const int b0 = bt * 8;
    const int H0 = ht * 16;

    // pre-wait prologue: stage W1 slice (independent of fft output)
#pragma unroll
    for (int it = 0; it < 8; it++) {
        int idx = t + it * 512;
        int j = idx >> 2, hq = idx & 3;
        float4 wv = *(const float4*)&W1[j * HID + H0 + hq * 4];
        ulonglong2* dst = (ulonglong2*)&w1d[j][hq * 4];
        dst[0] = make_ulonglong2(pk2(wv.x, wv.x), pk2(wv.y, wv.y));
        dst[1] = make_ulonglong2(pk2(wv.z, wv.z), pk2(wv.w, wv.w));
    }

    pdl_wait();

#pragma unroll
    for (int it = 0; it < 8; it++) {
        int idx = t + it * 512;
        int bp_ = idx >> 10, j = idx & 1023;
        csh[bp_][j] = pk2(g_c[(b0 + 2 * bp_) * NSEQ + j],
                          g_c[(b0 + 2 * bp_ + 1) * NSEQ + j]);
    }
    __syncthreads();

    const int bp = t & 3;
    const int h4 = (t >> 2) & 3;
    const int jq = t >> 4;
    const int j0 = jq * 32;

    u64 a0 = 0ull, a1 = 0ull, a2 = 0ull, a3 = 0ull;
#pragma unroll 8
    for (int j = j0; j < j0 + 32; j++) {
        u64 cv = csh[bp][j];
        const ulonglong2* wr = (const ulonglong2*)&w1d[j][h4 * 4];
        ulonglong2 w01 = wr[0];
        ulonglong2 w23 = wr[1];
        a0 = fma2(cv, w01.x, a0);
        a1 = fma2(cv, w01.y, a1);
        a2 = fma2(cv, w23.x, a2);
        a3 = fma2(cv, w23.y, a3);
    }
    {
        ulonglong2* rr = (ulonglong2*)&red[jq][bp * 16 + h4 * 4];
        rr[0] = make_ulonglong2(a0, a1);
        rr[1] = make_ulonglong2(a2, a3);
    }
    __syncthreads();

    if (t < 64) {
        int bp_ = t >> 4, h = t & 15;
        int cell = bp_ * 16 + h;
        u64 s0 = 0ull, s1 = 0ull, s2 = 0ull, s3 = 0ull;
#pragma unroll
        for (int q = 0; q < 32; q += 4) {
            s0 = add2(s0, red[q + 0][cell]);
            s1 = add2(s1, red[q + 1][cell]);
            s2 = add2(s2, red[q + 2][cell]);
            s3 = add2(s3, red[q + 3][cell]);
        }
        u64 s = add2(add2(s0, s1), add2(s2, s3));
        float va, vb;
        upk2(s, va, vb);
        float bb = b1[H0 + h];
        g_h1[(b0 + 2 * bp_) * HID + H0 + h]     = celu1(va + bb);
        g_h1[(b0 + 2 * bp_ + 1) * HID + H0 + h] = celu1(vb + bb);
        __threadfence();
    }
    __syncthreads();
    pdl_trigger();
}

// ---------------------------------------------------------------------------
// Kernel 3: layers 2+3 (PDL consumer). Weights staged pre-wait.
// 128 blocks, 256 threads.
// ---------------------------------------------------------------------------
#define MLP23_SMEM ((16384 + 128 + 128 + 512 + 128) * 4)

__global__ __launch_bounds__(256, 1)
void mlp23_kernel(const float* __restrict__ W2, const float* __restrict__ b2,
                  const float* __restrict__ W3, const float* __restrict__ b3,
                  float* __restrict__ out) {
    extern __shared__ float msm[];
    float* w2s = msm;               // [128*128]
    float* b2s = msm + 16384;       // [128]
    float* w3s = msm + 16512;       // [128]
    float* s2  = msm + 16640;       // [4][128]
    float* h1s = msm + 17152;       // [128]

    const int b = blockIdx.x, t = threadIdx.x;

    {   // pre-wait prologue: stage all weights
        const float4* __restrict__ W2v = (const float4*)W2;
        float4* w2sv = (float4*)w2s;
#pragma unroll
        for (int i = 0; i < 16; i++) w2sv[t + i * 256] = W2v[t + i * 256];
        if (t < 128) {
            b2s[t] = b2[t];
            w3s[t] = W3[t];
        }
    }

    pdl_wait();

    if (t < HID) h1s[t] = g_h1[b * HID + t];
    __syncthreads();

    const int kh = t >> 7, h = t & (HID - 1);
    const int k0 = kh * 64;
    float acc0 = 0.f, acc1 = 0.f, acc2 = 0.f, acc3 = 0.f;
#pragma unroll
    for (int k = k0; k < k0 + 64; k += 4) {
        acc0 += h1s[k + 0] * w2s[(k + 0) * HID + h];
        acc1 += h1s[k + 1] * w2s[(k + 1) * HID + h];
        acc2 += h1s[k + 2] * w2s[(k + 2) * HID + h];
        acc3 += h1s[k + 3] * w2s[(k + 3) * HID + h];
    }
    s2[kh * 128 + h] = (acc0 + acc1) + (acc2 + acc3);
    __syncthreads();

    if (t < HID) {
        float v = s2[t] + s2[128 + t] + b2s[t];
        s2[t] = celu1(v) * w3s[t];
    }
    __syncthreads();
#pragma unroll
    for (int o = 64; o > 0; o >>= 1) {
        if (t < o) s2[t] += s2[t + o];
        __syncthreads();
    }
    if (t == 0) out[b] = s2[0] + b3[0];
}

// ---------------------------------------------------------------------------
extern "C" void kernel_launch(void* const* d_in, const int* in_sizes, int n_in,
                              void* d_out, int out_size) {
    const float* x  = (const float*)d_in[0];
    const float* W1 = (const float*)d_in[1];
    const float* b1 = (const float*)d_in[2];
    const float* W2 = (const float*)d_in[3];
    const float* b2 = (const float*)d_in[4];
    const float* W3 = (const float*)d_in[5];
    const float* b3 = (const float*)d_in[6];
    float* out = (float*)d_out;

    static int configured = 0;
    if (!configured) {
        cudaFuncSetAttribute(gemm1_kernel,
                             cudaFuncAttributeMaxDynamicSharedMemorySize,
                             GEMM1_SMEM);
        cudaFuncSetAttribute(mlp23_kernel,
                             cudaFuncAttributeMaxDynamicSharedMemorySize,
                             MLP23_SMEM);
        configured = 1;
    }

    fftcorr_kernel<<<BATCH, 512>>>(x);

    cudaLaunchAttribute attrs[1];
    attrs[0].id = cudaLaunchAttributeProgrammaticStreamSerialization;
    attrs[0].val.programmaticStreamSerializationAllowed = 1;

    {   // gemm1 with PDL
        cudaLaunchConfig_t cfg = {};
        cfg.gridDim = dim3(128, 1, 1);
        cfg.blockDim = dim3(512, 1, 1);
        cfg.dynamicSmemBytes = GEMM1_SMEM;
        cfg.attrs = attrs;
        cfg.numAttrs = 1;
        cudaLaunchKernelEx(&cfg, gemm1_kernel, W1, b1);
    }
    {   // mlp23 with PDL
        cudaLaunchConfig_t cfg = {};
        cfg.gridDim = dim3(BATCH, 1, 1);
        cfg.blockDim = dim3(256, 1, 1);
        cfg.dynamicSmemBytes = MLP23_SMEM;
        cfg.attrs = attrs;
        cfg.numAttrs = 1;
        cudaLaunchKernelEx(&cfg, mlp23_kernel, W2, b2, W3, b3, out);
    }
}